// round 5
// baseline (speedup 1.0000x reference)
#include <cuda_runtime.h>

#define GN    128
#define GN2   (GN * GN)
#define GN3   (GN * GN * GN)
#define BIGV  1.0e5f
#define NITER 128
#define NTILES 2048           /* 128 i-planes * 16 j-blocks */

// Scratch ping-pong buffers + barrier state (allocation-free rule).
__device__ float g_bufA[GN3];
__device__ float g_bufB[GN3];
__device__ unsigned int          g_bar_count = 0;
__device__ volatile unsigned int g_bar_sense = 0;

__device__ __forceinline__ void tile_step(
    const float* __restrict__ src, const float* __restrict__ f,
    float* __restrict__ dst, int i, int j, int lane)
{
    const int idx = (i * GN + j) * GN + lane * 4;
    const float4 big4 = make_float4(BIGV, BIGV, BIGV, BIGV);

    const float4 uc  = *(const float4*)(src + idx);
    const float4 xm4 = (i > 0)      ? *(const float4*)(src + idx - GN2) : big4;
    const float4 xp4 = (i < GN - 1) ? *(const float4*)(src + idx + GN2) : big4;
    const float4 ym4 = (j > 0)      ? *(const float4*)(src + idx - GN)  : big4;
    const float4 yp4 = (j < GN - 1) ? *(const float4*)(src + idx + GN)  : big4;

    float left  = __shfl_up_sync(0xffffffffu, uc.w, 1);
    float right = __shfl_down_sync(0xffffffffu, uc.x, 1);
    if (lane == 0)  left  = BIGV;
    if (lane == 31) right = BIGV;

    const float* ucp = (const float*)&uc;
    const float* xmp = (const float*)&xm4;
    const float* xpp = (const float*)&xp4;
    const float* ymp = (const float*)&ym4;
    const float* ypp = (const float*)&yp4;

    // Cheap activity test: a1 = min of 6 neighbors.
    // Monotone: x >= a1 (fh >= 0.5) so a1 >= u => min(u,x) == u.
    bool act[4];
    bool anyact = false;
    #pragma unroll
    for (int c = 0; c < 4; ++c) {
        const float zm = (c == 0) ? left  : ucp[c - 1];
        const float zp = (c == 3) ? right : ucp[c + 1];
        const float a1 = fminf(fminf(fminf(xmp[c], xpp[c]), fminf(ymp[c], ypp[c])),
                               fminf(zm, zp));
        act[c] = (a1 < ucp[c]);
        anyact |= act[c];
    }

    float4 res = uc;
    float* rp = (float*)&res;

    if (anyact) {
        const float4 f4 = *(const float4*)(f + idx);
        const float* fp = (const float*)&f4;
        #pragma unroll
        for (int c = 0; c < 4; ++c) {
            if (!act[c]) continue;
            const float zm = (c == 0) ? left  : ucp[c - 1];
            const float zp = (c == 3) ? right : ucp[c + 1];
            const float ax = fminf(xmp[c], xpp[c]);
            const float ay = fminf(ymp[c], ypp[c]);
            const float az = fminf(zm, zp);
            // exact 3-sort via min/max network (matches jnp.sort)
            const float a1 = fminf(ax, fminf(ay, az));
            const float a3 = fmaxf(ax, fmaxf(ay, az));
            const float a2 = fmaxf(fminf(ax, ay), fminf(fmaxf(ax, ay), az));

            const float fh = fp[c];                     // h == 1.0
            const float x1 = a1 + fh;
            float x;
            if (x1 <= a2) {
                x = x1;
            } else {
                const float d  = a1 - a2;
                const float d2 = 2.0f * fh * fh - d * d;
                const float x2 = 0.5f * (a1 + a2 + sqrtf(fmaxf(d2, 0.0f)));
                if (x2 <= a3) {
                    x = x2;
                } else {
                    const float s  = a1 + a2 + a3;
                    const float q  = a1 * a1 + a2 * a2 + a3 * a3;
                    const float d3 = s * s - 3.0f * (q - fh * fh);
                    x = (s + sqrtf(fmaxf(d3, 0.0f))) / 3.0f;
                }
            }
            rp[c] = fminf(ucp[c], x);
        }
    }

    *(float4*)(dst + idx) = res;
}

__global__ void __launch_bounds__(256, 6) eik_persist(
    const float* __restrict__ u0,
    const float* __restrict__ f,
    float* __restrict__ out,
    int nblocks)
{
    const int lane = threadIdx.x;          // 0..31: k in float4s
    const int jy   = threadIdx.y;          // 0..7
    const int bid  = blockIdx.x;

    unsigned int local_sense = 0;
    const float* src = u0;

    for (int it = 0; it < NITER; ++it) {
        float* dst = (it == NITER - 1) ? out : ((it & 1) ? g_bufB : g_bufA);

        // Fixed tile ownership across iterations (L1 locality).
        for (int t = bid; t < NTILES; t += nblocks) {
            const int i = t >> 4;          // i-plane
            const int j = (t & 15) * 8 + jy;
            tile_step(src, f, dst, i, j, lane);
        }

        // ---- software grid barrier (sense reversal; state self-restores) ----
        local_sense ^= 1u;
        __syncthreads();
        if (threadIdx.x == 0 && threadIdx.y == 0) {
            __threadfence();
            unsigned int old = atomicInc(&g_bar_count, (unsigned)nblocks - 1u);
            if (old == (unsigned)nblocks - 1u) {
                g_bar_sense = local_sense;             // release (count wrapped to 0)
            } else {
                while (g_bar_sense != local_sense) __nanosleep(64);
            }
            __threadfence();
        }
        __syncthreads();

        src = dst;
    }
}

extern "C" void kernel_launch(void* const* d_in, const int* in_sizes, int n_in,
                              void* d_out, int out_size)
{
    const float* u0 = (const float*)d_in[0];
    const float* f  = (const float*)d_in[1];
    float* out      = (float*)d_out;

    // Conservative co-residency sizing (host queries: not stream ops, capture-safe).
    int dev = 0;
    cudaGetDevice(&dev);
    int sms = 0;
    cudaDeviceGetAttribute(&sms, cudaDevAttrMultiProcessorCount, dev);
    int bpsm = 0;
    cudaOccupancyMaxActiveBlocksPerMultiprocessor(&bpsm, eik_persist, 256, 0);
    if (bpsm < 1) bpsm = 1;
    int nblocks = sms * bpsm;
    if (nblocks > NTILES) nblocks = NTILES;

    const dim3 blk(32, 8, 1);
    eik_persist<<<nblocks, blk>>>(u0, f, out, nblocks);
}